// round 2
// baseline (speedup 1.0000x reference)
#include <cuda_runtime.h>
#include <cstdint>

#define BB 64
#define RR 32
#define NN 16384
#define DD 64
#define OO 8
#define CHUNKS 8
#define NC (NN / CHUNKS)   // 2048 rows per chunk-block

// Per-chunk partials (plain stores each replay; no zeroing needed).
__device__ float g_part[BB * CHUNKS * DD];
__device__ float g_pcnt[BB * CHUNKS];
// Arrival counters: zero-initialized at load; last arriver resets to 0,
// so every graph replay sees the same initial state (deterministic).
__device__ int g_arrive[BB];

// One block per (b, chunk): mask scan -> compact -> sparse gather+normalize
// -> partial store. The last-arriving block per b performs the finalize.
__global__ void __launch_bounds__(256) fused_kernel(
    const float* __restrict__ h_context,
    const float* __restrict__ l_local,
    const float* __restrict__ lambda_so,
    const int* __restrict__ center_o,
    const int* __restrict__ o_types,
    const unsigned int* __restrict__ adj,   // bool-as-32-bit word (i32 or f32 0/1)
    const unsigned int* __restrict__ two,
    float* __restrict__ out)
{
    __shared__ int s_idx[NC];
    __shared__ int s_count;
    __shared__ float s_acc[DD];
    __shared__ int s_last;

    const int b   = blockIdx.x / CHUNKS;
    const int c   = blockIdx.x % CHUNKS;
    const int tid = threadIdx.x;
    const int warp = tid >> 5;
    const int lane = tid & 31;

    if (tid == 0) s_count = 0;
    if (tid < DD) s_acc[tid] = 0.0f;
    __syncthreads();

    const int co = center_o[b];
    const int base = b * NN + c * NC;

    const int4*  ot4 = reinterpret_cast<const int4*>(o_types + base);
    const uint4* a4  = reinterpret_cast<const uint4*>(adj + base);
    const uint4* t4  = reinterpret_cast<const uint4*>(two + base);

    // Phase A: vectorized mask scan + compaction (density ~0.74%)
    for (int i = tid; i < NC / 4; i += 256) {
        int4  ot = ot4[i];
        uint4 a  = a4[i];
        uint4 t  = t4[i];
        int n0 = c * NC + i * 4;
        if (ot.x == co && (a.x | t.x)) s_idx[atomicAdd(&s_count, 1)] = n0 + 0;
        if (ot.y == co && (a.y | t.y)) s_idx[atomicAdd(&s_count, 1)] = n0 + 1;
        if (ot.z == co && (a.z | t.z)) s_idx[atomicAdd(&s_count, 1)] = n0 + 2;
        if (ot.w == co && (a.w | t.w)) s_idx[atomicAdd(&s_count, 1)] = n0 + 3;
    }
    __syncthreads();

    const int cnt = s_count;

    // Phase B: warps cooperatively normalize+accumulate compacted rows.
    // Each lane owns 2 of 64 dims (float2).
    float accx = 0.0f, accy = 0.0f;
    const float2* ctx2 = reinterpret_cast<const float2*>(
        h_context + (size_t)b * NN * DD);
    for (int i = warp; i < cnt; i += 8) {
        int n = s_idx[i];
        float2 x = __ldg(ctx2 + (size_t)n * (DD / 2) + lane);
        float sq = x.x * x.x + x.y * x.y;
        #pragma unroll
        for (int o = 16; o; o >>= 1)
            sq += __shfl_xor_sync(0xffffffffu, sq, o);
        float rinv = rsqrtf(fmaxf(sq, 1e-12f));
        accx += x.x * rinv;
        accy += x.y * rinv;
    }
    atomicAdd(&s_acc[2 * lane + 0], accx);
    atomicAdd(&s_acc[2 * lane + 1], accy);
    __syncthreads();

    // Store partials (plain stores; no pre-zero required).
    if (tid < DD) g_part[(b * CHUNKS + c) * DD + tid] = s_acc[tid];
    if (tid == 0) g_pcnt[b * CHUNKS + c] = (float)cnt;

    // Arrival protocol: publish partials, then count arrivals.
    __threadfence();
    __syncthreads();
    if (tid == 0) {
        int prev = atomicAdd(&g_arrive[b], 1);
        s_last = (prev == CHUNKS - 1) ? 1 : 0;
        if (s_last) g_arrive[b] = 0;   // restore replay invariant
    }
    __syncthreads();
    if (!s_last) return;

    // ---- Finalize for this b (only the last-arriving block runs this) ----
    __threadfence();  // acquire partials published by peer blocks

    __shared__ float sv[DD];
    __shared__ float scnt;
    if (tid < DD) {
        float s = 0.0f;
        #pragma unroll
        for (int cc = 0; cc < CHUNKS; cc++)
            s += g_part[(b * CHUNKS + cc) * DD + tid];
        sv[tid] = s;
    }
    if (tid == 0) {
        float s = 0.0f;
        #pragma unroll
        for (int cc = 0; cc < CHUNKS; cc++)
            s += g_pcnt[b * CHUNKS + cc];
        scnt = s;
    }
    __syncthreads();

    // 8 warps x 4 rows each = 32 rows. Each lane owns 2 dims (float2).
    const float cval = scnt;
    #pragma unroll
    for (int rr = 0; rr < 4; rr++) {
        int r = warp + rr * 8;
        const float2* row = reinterpret_cast<const float2*>(
            l_local + ((size_t)b * RR + r) * DD);
        float2 x = row[lane];
        float sq = x.x * x.x + x.y * x.y;
        float dp = x.x * sv[2 * lane] + x.y * sv[2 * lane + 1];
        #pragma unroll
        for (int o = 16; o; o >>= 1) {
            sq += __shfl_xor_sync(0xffffffffu, sq, o);
            dp += __shfl_xor_sync(0xffffffffu, dp, o);
        }
        if (lane == 0) {
            float rinv = rsqrtf(fmaxf(sq, 1e-12f));
            float avg = dp * rinv / fmaxf(cval, 1e-9f);
            float lam = lambda_so[r * OO + co];
            float w = fmaxf(lam / fmaxf(cval, 1.0f), 0.0f) * (1.0f - avg);
            out[b * RR + r] = w;
        }
    }
}

extern "C" void kernel_launch(void* const* d_in, const int* in_sizes, int n_in,
                              void* d_out, int out_size) {
    const float*        l_local   = (const float*)d_in[0];
    const float*        h_context = (const float*)d_in[1];
    const float*        lambda_so = (const float*)d_in[2];
    const int*          center_o  = (const int*)d_in[3];
    const int*          o_types   = (const int*)d_in[4];
    const unsigned int* adj       = (const unsigned int*)d_in[5];
    const unsigned int* two       = (const unsigned int*)d_in[6];
    float*              out       = (float*)d_out;

    fused_kernel<<<BB * CHUNKS, 256>>>(h_context, l_local, lambda_so,
                                       center_o, o_types, adj, two, out);
}